// round 3
// baseline (speedup 1.0000x reference)
#include <cuda_runtime.h>
#include <cuda_bf16.h>
#include <math.h>

#define TT 2048
#define BB 512
#define HH 128
#define GG 512
#define ROWS 4
#define BM1 128
#define BN1 64

typedef unsigned long long u64;
typedef unsigned int u32;

// scratch (static device globals: allowed; no cudaMalloc anywhere)
static __device__ __nv_bfloat16 g_y0[(size_t)BB * TT * HH];   // layer-0 outputs (bf16)
static __device__ __nv_bfloat16 g_xg1[(size_t)BB * TT * GG];  // layer-1 input gates + bias (bf16)
static __device__ float g_h1f[BB * HH];                       // final hidden of layer 1

__device__ __forceinline__ float tanha(float x) {
    asm("tanh.approx.f32 %0, %0;" : "+f"(x));
    return x;
}
__device__ __forceinline__ float sigm(float x) { return fmaf(tanha(0.5f * x), 0.5f, 0.5f); }

__device__ __forceinline__ void ffma2(u64 &d, u64 a, u64 b) {
    asm("fma.rn.f32x2 %0, %1, %2, %0;" : "+l"(d) : "l"(a), "l"(b));
}
// bf16x2 (lo=w_k, hi=w_{k+1}) -> packed f32x2 (bf16->f32 is a left shift by 16)
__device__ __forceinline__ u64 bfpair(u32 u) {
    u32 lo = u << 16;
    u32 hi = u & 0xffff0000u;
    u64 r;
    asm("mov.b64 %0, {%1, %2};" : "=l"(r) : "r"(lo), "r"(hi));
    return r;
}
__device__ __forceinline__ float2 upk(u64 v) {
    float a, b;
    asm("mov.b64 {%0, %1}, %2;" : "=f"(a), "=f"(b) : "l"(v));
    return make_float2(a, b);
}
__device__ __forceinline__ u32 pbf2(float a, float b) {
    __nv_bfloat162 t = __floats2bfloat162_rn(a, b);
    return *(u32 *)&t;
}

// Load recurrent weights W[512][128] fp32 -> smem bf16, layout Ws[k4][g] = {bf16x2(k,k+1), bf16x2(k+2,k+3)}
__device__ __forceinline__ void load_w(uint2 *Ws, const float *__restrict__ W, int tid) {
    for (int i = tid; i < 32 * GG; i += 512) {
        int g = i & (GG - 1);
        int k4 = i >> 9;
        float4 w = *reinterpret_cast<const float4 *>(W + (size_t)g * HH + k4 * 4);
        Ws[k4 * GG + g] = make_uint2(pbf2(w.x, w.y), pbf2(w.z, w.w));
    }
}

// d[r] = sum_k W[g][k] * h[r][k], r=0..3. Weights bf16 in smem, h fp32 in smem, packed f32x2 FMAs.
__device__ __forceinline__ void dot4(const uint2 *__restrict__ Ws, const float *__restrict__ hs,
                                     int g, float *d) {
    u64 acc0 = 0, acc1 = 0, acc2 = 0, acc3 = 0;
    const ulonglong2 *h0 = (const ulonglong2 *)(hs);
    const ulonglong2 *h1 = (const ulonglong2 *)(hs + HH);
    const ulonglong2 *h2 = (const ulonglong2 *)(hs + 2 * HH);
    const ulonglong2 *h3 = (const ulonglong2 *)(hs + 3 * HH);
#pragma unroll 8
    for (int k4 = 0; k4 < 32; ++k4) {
        uint2 w = Ws[k4 * GG + g];
        u64 w0 = bfpair(w.x), w1 = bfpair(w.y);
        ulonglong2 a0 = h0[k4], a1 = h1[k4], a2 = h2[k4], a3 = h3[k4];
        ffma2(acc0, w0, a0.x); ffma2(acc0, w1, a0.y);
        ffma2(acc1, w0, a1.x); ffma2(acc1, w1, a1.y);
        ffma2(acc2, w0, a2.x); ffma2(acc2, w1, a2.y);
        ffma2(acc3, w0, a3.x); ffma2(acc3, w1, a3.y);
    }
    float2 p;
    p = upk(acc0); d[0] = p.x + p.y;
    p = upk(acc1); d[1] = p.x + p.y;
    p = upk(acc2); d[2] = p.x + p.y;
    p = upk(acc3); d[3] = p.x + p.y;
}

// ---------------- K0: layer-0 LSTM. 128 blocks x 512 threads, 4 batch rows per block ----------------
extern "C" __global__ void __launch_bounds__(512, 1)
k_lstm0(const float *__restrict__ x, const float *__restrict__ Wih0,
        const float *__restrict__ Whh0, const float *__restrict__ bih0,
        const float *__restrict__ bhh0) {
    extern __shared__ char smem[];
    uint2 *Ws = (uint2 *)smem;                                 // 131072 B
    float2 *feats = (float2 *)(smem + 131072);                 // 65536 B  [4][2048]
    float *hs = (float *)(smem + 131072 + 65536);              // 2048 B   [4][128]
    float *stage = (float *)(smem + 131072 + 65536 + 2048);    // 8192 B   [4][512]
    const int tid = threadIdx.x;
    const int rb = blockIdx.x * ROWS;
    const int r = tid >> 7;         // phase-2 identity: batch row 0..3
    const int j = tid & (HH - 1);   // phase-2 identity: hidden unit 0..127

    load_w(Ws, Whh0, tid);
    for (int i = tid; i < ROWS * TT; i += 512) {
        int rr = i >> 11, t = i & (TT - 1);
        const float *xp = x + ((size_t)(rb + rr) * TT + t) * 6;
        float a0 = xp[0], a1 = xp[1], a2 = xp[2];
        float g0 = xp[3], g1 = xp[4], g2 = xp[5];
        feats[rr * TT + t] = make_float2(sqrtf(a0 * a0 + a1 * a1 + a2 * a2),
                                         sqrtf(g0 * g0 + g1 * g1 + g2 * g2));
    }
    hs[tid] = 0.f;

    // per-thread input weights / fused biases for unit (r, j)
    float wi0 = Wih0[j * 2],            wi1 = Wih0[j * 2 + 1];
    float wf0 = Wih0[(j + HH) * 2],     wf1 = Wih0[(j + HH) * 2 + 1];
    float wg0 = Wih0[(j + 2 * HH) * 2], wg1 = Wih0[(j + 2 * HH) * 2 + 1];
    float wo0 = Wih0[(j + 3 * HH) * 2], wo1 = Wih0[(j + 3 * HH) * 2 + 1];
    float bi = bih0[j] + bhh0[j];
    float bf = bih0[j + HH] + bhh0[j + HH];
    float bg = bih0[j + 2 * HH] + bhh0[j + 2 * HH];
    float bo = bih0[j + 3 * HH] + bhh0[j + 3 * HH];
    float c = 0.f;
    __syncthreads();

    __nv_bfloat16 *yout = g_y0 + ((size_t)(rb + r) * TT) * HH + j;
#pragma unroll 1
    for (int t = 0; t < TT; ++t) {
        float d[4];
        dot4(Ws, hs, tid, d);  // phase-1 identity: gate g = tid
        stage[0 * GG + tid] = d[0];
        stage[1 * GG + tid] = d[1];
        stage[2 * GG + tid] = d[2];
        stage[3 * GG + tid] = d[3];
        __syncthreads();
        float2 f2 = feats[r * TT + t];
        float gi = stage[r * GG + j]          + fmaf(wi0, f2.x, fmaf(wi1, f2.y, bi));
        float gf = stage[r * GG + j + HH]     + fmaf(wf0, f2.x, fmaf(wf1, f2.y, bf));
        float gg = stage[r * GG + j + 2 * HH] + fmaf(wg0, f2.x, fmaf(wg1, f2.y, bg));
        float go = stage[r * GG + j + 3 * HH] + fmaf(wo0, f2.x, fmaf(wo1, f2.y, bo));
        c = sigm(gf) * c + sigm(gi) * tanha(gg);
        float h = sigm(go) * tanha(c);
        hs[r * HH + j] = h;
        yout[(size_t)t * HH] = __float2bfloat16(h);
        __syncthreads();
    }
}

// ---------------- K1: xg1 = y0 @ Wih1^T + (bih1+bhh1). Plain fp32 tiled GEMM ----------------
extern "C" __global__ void __launch_bounds__(256, 2)
k_gemm1(const float *__restrict__ Wih1, const float *__restrict__ bih1,
        const float *__restrict__ bhh1) {
    extern __shared__ char smem[];
    float *As = (float *)smem;             // [k][m] 128x128 fp32 = 65536 B (transposed)
    float *Bs = (float *)(smem + 65536);   // [k][n] 128x64 fp32 = 32768 B (transposed)
    const int tid = threadIdx.x;
    const size_t bt0 = (size_t)blockIdx.x * BM1;
    const int g0 = blockIdx.y * BN1;

    // A tile: 128 bt-rows x 128 k, bf16 -> fp32 transposed
    for (int v = tid; v < (BM1 * HH) / 8; v += 256) {
        int m = v >> 4, kc = v & 15;
        uint4 raw = *reinterpret_cast<const uint4 *>(g_y0 + (bt0 + m) * HH + kc * 8);
        const unsigned short *us = (const unsigned short *)&raw;
#pragma unroll
        for (int u = 0; u < 8; ++u)
            As[(kc * 8 + u) * BM1 + m] = __uint_as_float(((u32)us[u]) << 16);
    }
    // B tile: 64 gates x 128 k fp32, transposed
    for (int v = tid; v < (BN1 * HH) / 4; v += 256) {
        int gl = v >> 5, kc = v & 31;
        float4 w = *reinterpret_cast<const float4 *>(Wih1 + (size_t)(g0 + gl) * HH + kc * 4);
        Bs[(kc * 4 + 0) * BN1 + gl] = w.x;
        Bs[(kc * 4 + 1) * BN1 + gl] = w.y;
        Bs[(kc * 4 + 2) * BN1 + gl] = w.z;
        Bs[(kc * 4 + 3) * BN1 + gl] = w.w;
    }
    __syncthreads();

    const int m0 = (tid & 15) * 8;
    const int n0 = (tid >> 4) * 4;
    float acc[8][4];
#pragma unroll
    for (int i = 0; i < 8; ++i)
#pragma unroll
        for (int jn = 0; jn < 4; ++jn) acc[i][jn] = 0.f;

#pragma unroll 4
    for (int k = 0; k < HH; ++k) {
        float4 a0 = *reinterpret_cast<const float4 *>(As + k * BM1 + m0);
        float4 a1 = *reinterpret_cast<const float4 *>(As + k * BM1 + m0 + 4);
        float4 b = *reinterpret_cast<const float4 *>(Bs + k * BN1 + n0);
        float am[8] = {a0.x, a0.y, a0.z, a0.w, a1.x, a1.y, a1.z, a1.w};
        float bn[4] = {b.x, b.y, b.z, b.w};
#pragma unroll
        for (int i = 0; i < 8; ++i)
#pragma unroll
            for (int jn = 0; jn < 4; ++jn)
                acc[i][jn] = fmaf(am[i], bn[jn], acc[i][jn]);
    }
    float bias[4];
#pragma unroll
    for (int jn = 0; jn < 4; ++jn) bias[jn] = bih1[g0 + n0 + jn] + bhh1[g0 + n0 + jn];
#pragma unroll
    for (int i = 0; i < 8; ++i) {
        __nv_bfloat16 *p = g_xg1 + (bt0 + m0 + i) * GG + g0 + n0;
        __nv_bfloat162 v01 = __floats2bfloat162_rn(acc[i][0] + bias[0], acc[i][1] + bias[1]);
        __nv_bfloat162 v23 = __floats2bfloat162_rn(acc[i][2] + bias[2], acc[i][3] + bias[3]);
        *reinterpret_cast<__nv_bfloat162 *>(p) = v01;
        *reinterpret_cast<__nv_bfloat162 *>(p + 2) = v23;
    }
}

// ---------------- K2: layer-1 LSTM (xg pre-computed). Writes only final h ----------------
extern "C" __global__ void __launch_bounds__(512, 1)
k_lstm1(const float *__restrict__ Whh1) {
    extern __shared__ char smem[];
    uint2 *Ws = (uint2 *)smem;                       // 131072 B
    float *hs = (float *)(smem + 131072);            // 2048 B
    float *stage = (float *)(smem + 131072 + 2048);  // 8192 B
    const int tid = threadIdx.x;
    const int rb = blockIdx.x * ROWS;
    const int r = tid >> 7, j = tid & (HH - 1);

    load_w(Ws, Whh1, tid);
    hs[tid] = 0.f;
    float c = 0.f;
    __syncthreads();

    const __nv_bfloat16 *xg = g_xg1 + ((size_t)(rb + r) * TT) * GG + j;
#pragma unroll 1
    for (int t = 0; t < TT; ++t) {
        // prefetch this step's input-gate values; ~600cyc latency hides under the ~2500cyc dot
        const __nv_bfloat16 *xp = xg + (size_t)t * GG;
        float xi = __bfloat162float(xp[0]);
        float xf = __bfloat162float(xp[HH]);
        float xgg = __bfloat162float(xp[2 * HH]);
        float xo = __bfloat162float(xp[3 * HH]);

        float d[4];
        dot4(Ws, hs, tid, d);
        stage[0 * GG + tid] = d[0];
        stage[1 * GG + tid] = d[1];
        stage[2 * GG + tid] = d[2];
        stage[3 * GG + tid] = d[3];
        __syncthreads();
        float gi = stage[r * GG + j] + xi;
        float gf = stage[r * GG + j + HH] + xf;
        float gg = stage[r * GG + j + 2 * HH] + xgg;
        float go = stage[r * GG + j + 3 * HH] + xo;
        c = sigm(gf) * c + sigm(gi) * tanha(gg);
        float h = sigm(go) * tanha(c);
        hs[r * HH + j] = h;
        if (t == TT - 1) g_h1f[(rb + r) * HH + j] = h;
        __syncthreads();
    }
}

// ---------------- K3: classifier MLP + double softmax. 512 blocks x 128 threads ----------------
extern "C" __global__ void __launch_bounds__(128)
k_cls(const float *__restrict__ W1, const float *__restrict__ b1,
      const float *__restrict__ W2, const float *__restrict__ b2,
      const float *__restrict__ W3, const float *__restrict__ b3,
      float *__restrict__ out) {
    __shared__ float hb[128], z1[128], z2[64], z3[8];
    const int tid = threadIdx.x;
    const int row = blockIdx.x;
    hb[tid] = g_h1f[row * HH + tid];
    __syncthreads();
    float a = b1[tid];
#pragma unroll 4
    for (int k = 0; k < 128; ++k) a = fmaf(W1[tid * 128 + k], hb[k], a);
    z1[tid] = fmaxf(a, 0.f);
    __syncthreads();
    if (tid < 64) {
        float s = b2[tid];
#pragma unroll 4
        for (int k = 0; k < 128; ++k) s = fmaf(W2[tid * 128 + k], z1[k], s);
        z2[tid] = fmaxf(s, 0.f);
    }
    __syncthreads();
    if (tid < 6) {
        float s = b3[tid];
#pragma unroll 4
        for (int k = 0; k < 64; ++k) s = fmaf(W3[tid * 64 + k], z2[k], s);
        z3[tid] = s;
    }
    __syncthreads();
    if (tid == 0) {
        float v[6];
#pragma unroll
        for (int i = 0; i < 6; ++i) v[i] = z3[i];
#pragma unroll
        for (int p = 0; p < 2; ++p) {
            float m = v[0];
            for (int i = 1; i < 6; ++i) m = fmaxf(m, v[i]);
            float s = 0.f;
            for (int i = 0; i < 6; ++i) { v[i] = expf(v[i] - m); s += v[i]; }
            float inv = 1.f / s;
            for (int i = 0; i < 6; ++i) v[i] *= inv;
        }
        for (int i = 0; i < 6; ++i) out[row * 6 + i] = v[i];
    }
}

extern "C" void kernel_launch(void *const *d_in, const int *in_sizes, int n_in,
                              void *d_out, int out_size) {
    const float *x = (const float *)d_in[0];
    const float *Wih0 = (const float *)d_in[1];
    const float *Whh0 = (const float *)d_in[2];
    const float *bih0 = (const float *)d_in[3];
    const float *bhh0 = (const float *)d_in[4];
    const float *Wih1 = (const float *)d_in[5];
    const float *Whh1 = (const float *)d_in[6];
    const float *bih1 = (const float *)d_in[7];
    const float *bhh1 = (const float *)d_in[8];
    const float *W1 = (const float *)d_in[9];
    const float *b1 = (const float *)d_in[10];
    const float *W2 = (const float *)d_in[11];
    const float *b2 = (const float *)d_in[12];
    const float *W3 = (const float *)d_in[13];
    const float *b3 = (const float *)d_in[14];
    float *out = (float *)d_out;

    const int SMEM0 = 131072 + 65536 + 2048 + 8192;  // 206848
    const int SMEM1 = 65536 + 32768;                 // 98304
    const int SMEM2 = 131072 + 2048 + 8192;          // 141312
    cudaFuncSetAttribute(k_lstm0, cudaFuncAttributeMaxDynamicSharedMemorySize, SMEM0);
    cudaFuncSetAttribute(k_gemm1, cudaFuncAttributeMaxDynamicSharedMemorySize, SMEM1);
    cudaFuncSetAttribute(k_lstm1, cudaFuncAttributeMaxDynamicSharedMemorySize, SMEM2);

    k_lstm0<<<BB / ROWS, 512, SMEM0>>>(x, Wih0, Whh0, bih0, bhh0);
    k_gemm1<<<dim3((BB * TT) / BM1, GG / BN1), 256, SMEM1>>>(Wih1, bih1, bhh1);
    k_lstm1<<<BB / ROWS, 512, SMEM2>>>(Whh1);
    k_cls<<<BB, 128>>>(W1, b1, W2, b2, W3, b3, out);
}

// round 4
// speedup vs baseline: 1.5385x; 1.5385x over previous
#include <cuda_runtime.h>
#include <cuda_bf16.h>
#include <math.h>

#define TT 2048
#define BB 512
#define HH 128
#define GG 512
#define ROWS 4

typedef unsigned long long u64;
typedef unsigned int u32;

// scratch (static device globals: allowed; no cudaMalloc anywhere)
static __device__ __nv_bfloat16 g_y0[(size_t)BB * TT * HH];   // layer-0 outputs (bf16)
static __device__ __nv_bfloat16 g_xg1[(size_t)BB * TT * GG];  // layer-1 input gates + bias (bf16)
static __device__ float g_h1f[BB * HH];                       // final hidden of layer 1

__device__ __forceinline__ float tanha(float x) {
    asm("tanh.approx.f32 %0, %0;" : "+f"(x));
    return x;
}
__device__ __forceinline__ float sigm(float x) { return fmaf(tanha(0.5f * x), 0.5f, 0.5f); }

__device__ __forceinline__ void ffma2(u64 &d, u64 a, u64 b) {
    asm("fma.rn.f32x2 %0, %1, %2, %0;" : "+l"(d) : "l"(a), "l"(b));
}
// bf16x2 (lo=w_k, hi=w_{k+1}) -> packed f32x2 (bf16->f32 == <<16)
__device__ __forceinline__ u64 bfpair(u32 u) {
    u32 lo = u << 16;
    u32 hi = u & 0xffff0000u;
    u64 r;
    asm("mov.b64 %0, {%1, %2};" : "=l"(r) : "r"(lo), "r"(hi));
    return r;
}
__device__ __forceinline__ float2 upk(u64 v) {
    float a, b;
    asm("mov.b64 {%0, %1}, %2;" : "=f"(a), "=f"(b) : "l"(v));
    return make_float2(a, b);
}
__device__ __forceinline__ u32 pbf2(float a, float b) {
    __nv_bfloat162 t = __floats2bfloat162_rn(a, b);
    return *(u32 *)&t;
}

// recurrent weights W[512][128] fp32 -> smem bf16, Ws[k4][g] = {bf16x2(k,k+1), bf16x2(k+2,k+3)}
__device__ __forceinline__ void load_w(uint2 *Ws, const float *__restrict__ W, int tid, int nthr) {
    for (int i = tid; i < 32 * GG; i += nthr) {
        int g = i & (GG - 1);
        int k4 = i >> 9;
        float4 w = *reinterpret_cast<const float4 *>(W + (size_t)g * HH + k4 * 4);
        Ws[k4 * GG + g] = make_uint2(pbf2(w.x, w.y), pbf2(w.z, w.w));
    }
}

// half-K dot: d[r] = sum_{k in [64*kh, 64*kh+64)} W[g][k] * h[r][k]
__device__ __forceinline__ void dot4h(const uint2 *__restrict__ Ws, const float *__restrict__ hs,
                                      int g, int k4b, float *d) {
    u64 acc0 = 0, acc1 = 0, acc2 = 0, acc3 = 0;
    const ulonglong2 *h0 = (const ulonglong2 *)(hs) + k4b;
    const ulonglong2 *h1 = (const ulonglong2 *)(hs + HH) + k4b;
    const ulonglong2 *h2 = (const ulonglong2 *)(hs + 2 * HH) + k4b;
    const ulonglong2 *h3 = (const ulonglong2 *)(hs + 3 * HH) + k4b;
    const uint2 *wp = Ws + (size_t)k4b * GG + g;
#pragma unroll 8
    for (int i = 0; i < 16; ++i) {
        uint2 w = wp[i * GG];
        u64 w0 = bfpair(w.x), w1 = bfpair(w.y);
        ulonglong2 a0 = h0[i], a1 = h1[i], a2 = h2[i], a3 = h3[i];
        ffma2(acc0, w0, a0.x); ffma2(acc0, w1, a0.y);
        ffma2(acc1, w0, a1.x); ffma2(acc1, w1, a1.y);
        ffma2(acc2, w0, a2.x); ffma2(acc2, w1, a2.y);
        ffma2(acc3, w0, a3.x); ffma2(acc3, w1, a3.y);
    }
    float2 p;
    p = upk(acc0); d[0] = p.x + p.y;
    p = upk(acc1); d[1] = p.x + p.y;
    p = upk(acc2); d[2] = p.x + p.y;
    p = upk(acc3); d[3] = p.x + p.y;
}

// ---------------- K0: layer-0 LSTM. 128 blocks x 1024 threads (split-K), 4 batch rows/block ----------------
extern "C" __global__ void __launch_bounds__(1024, 1)
k_lstm0(const float *__restrict__ x, const float *__restrict__ Wih0,
        const float *__restrict__ Whh0, const float *__restrict__ bih0,
        const float *__restrict__ bhh0) {
    extern __shared__ char smem[];
    uint2 *Ws = (uint2 *)smem;                        // 131072 B
    float2 *feats = (float2 *)(smem + 131072);        // 65536 B  [4][2048]
    float *hs = (float *)(smem + 196608);             // 2048 B   [4][128]
    float *stage = (float *)(smem + 198656);          // 16384 B  [2][4][512]
    float2 *wih2 = (float2 *)(smem + 215040);         // 4096 B   [512]
    float *bsum = (float *)(smem + 219136);           // 2048 B   [512]
    const int tid = threadIdx.x;
    const int rb = blockIdx.x * ROWS;
    const int g = tid & (GG - 1);
    const int kh = tid >> 9;                 // dot identity: k-half
    const int r = (tid >> 7) & 3;            // pointwise identity (tid<512)
    const int j = tid & (HH - 1);

    load_w(Ws, Whh0, tid, 1024);
    for (int i = tid; i < ROWS * TT; i += 1024) {
        int rr = i >> 11, t = i & (TT - 1);
        const float *xp = x + ((size_t)(rb + rr) * TT + t) * 6;
        float a0 = xp[0], a1 = xp[1], a2 = xp[2];
        float g0 = xp[3], g1 = xp[4], g2 = xp[5];
        feats[rr * TT + t] = make_float2(sqrtf(a0 * a0 + a1 * a1 + a2 * a2),
                                         sqrtf(g0 * g0 + g1 * g1 + g2 * g2));
    }
    if (tid < GG) {
        hs[tid & 511] = 0.f;  // hs has 512 entries
        wih2[tid] = make_float2(Wih0[tid * 2], Wih0[tid * 2 + 1]);
        bsum[tid] = bih0[tid] + bhh0[tid];
    }
    float c = 0.f;
    __syncthreads();

    __nv_bfloat16 *yout = g_y0 + ((size_t)(rb + r) * TT) * HH + j;
#pragma unroll 1
    for (int t = 0; t < TT; ++t) {
        float d[4];
        dot4h(Ws, hs, g, kh * 16, d);
        float *st = stage + kh * 2048 + g;
        st[0 * GG] = d[0];
        st[1 * GG] = d[1];
        st[2 * GG] = d[2];
        st[3 * GG] = d[3];
        __syncthreads();
        if (tid < 512) {
            float2 f2 = feats[r * TT + t];
            const float *s0 = stage + r * GG;
            const float *s1 = stage + 2048 + r * GG;
            float2 wi = wih2[j], wf = wih2[j + HH], wg = wih2[j + 2 * HH], wo = wih2[j + 3 * HH];
            float gi = s0[j]          + s1[j]          + fmaf(wi.x, f2.x, fmaf(wi.y, f2.y, bsum[j]));
            float gf = s0[j + HH]     + s1[j + HH]     + fmaf(wf.x, f2.x, fmaf(wf.y, f2.y, bsum[j + HH]));
            float gg = s0[j + 2 * HH] + s1[j + 2 * HH] + fmaf(wg.x, f2.x, fmaf(wg.y, f2.y, bsum[j + 2 * HH]));
            float go = s0[j + 3 * HH] + s1[j + 3 * HH] + fmaf(wo.x, f2.x, fmaf(wo.y, f2.y, bsum[j + 3 * HH]));
            c = sigm(gf) * c + sigm(gi) * tanha(gg);
            float h = sigm(go) * tanha(c);
            hs[tid] = h;
            yout[(size_t)t * HH] = __float2bfloat16(h);
        }
        __syncthreads();
    }
}

// ---------------- K1: xg1 = y0 @ Wih1^T + bias, bf16 HMMA (mma.sync m16n8k16) ----------------
__device__ __forceinline__ void mma16816(float *c, const u32 *a, const u32 *b) {
    asm volatile(
        "mma.sync.aligned.m16n8k16.row.col.f32.bf16.bf16.f32 "
        "{%0,%1,%2,%3}, {%4,%5,%6,%7}, {%8,%9}, {%0,%1,%2,%3};"
        : "+f"(c[0]), "+f"(c[1]), "+f"(c[2]), "+f"(c[3])
        : "r"(a[0]), "r"(a[1]), "r"(a[2]), "r"(a[3]), "r"(b[0]), "r"(b[1]));
}

#define LDA 136  // padded bf16 row stride (272 B): conflict-free fragment loads

extern "C" __global__ void __launch_bounds__(256)
k_gemm1(const float *__restrict__ Wih1, const float *__restrict__ bih1,
        const float *__restrict__ bhh1) {
    extern __shared__ char smem[];
    __nv_bfloat16 *As = (__nv_bfloat16 *)smem;            // [128][136]
    __nv_bfloat16 *Bs = As + 128 * LDA;                   // [128][136]
    const int tid = threadIdx.x;
    const size_t bt0 = (size_t)blockIdx.x * 128;
    const int g0 = blockIdx.y * 128;

    // A tile: y0 rows, already bf16
    for (int v = tid; v < 128 * 16; v += 256) {
        int m = v >> 4, kc = v & 15;
        uint4 raw = *reinterpret_cast<const uint4 *>(g_y0 + (bt0 + m) * HH + kc * 8);
        *reinterpret_cast<uint4 *>(As + m * LDA + kc * 8) = raw;
    }
    // B tile: Wih1[g0..g0+128][0..128] fp32 -> bf16
    for (int v = tid; v < 128 * 32; v += 256) {
        int gl = v >> 5, kc = v & 31;
        float4 w = *reinterpret_cast<const float4 *>(Wih1 + (size_t)(g0 + gl) * HH + kc * 4);
        __nv_bfloat162 p0 = __floats2bfloat162_rn(w.x, w.y);
        __nv_bfloat162 p1 = __floats2bfloat162_rn(w.z, w.w);
        *reinterpret_cast<__nv_bfloat162 *>(Bs + gl * LDA + kc * 4) = p0;
        *reinterpret_cast<__nv_bfloat162 *>(Bs + gl * LDA + kc * 4 + 2) = p1;
    }
    __syncthreads();

    const int w = tid >> 5, lane = tid & 31, gid = lane >> 2, tig = lane & 3;
    const int wm = w & 1, wn = w >> 1;  // 2 m-warps x 4 n-warps; warp tile m64 x n32
    float acc[4][4][4];
#pragma unroll
    for (int mt = 0; mt < 4; ++mt)
#pragma unroll
        for (int nt = 0; nt < 4; ++nt)
#pragma unroll
            for (int i = 0; i < 4; ++i) acc[mt][nt][i] = 0.f;

#pragma unroll
    for (int ks = 0; ks < 8; ++ks) {
        const int k0 = ks * 16;
        u32 a[4][4], b[4][2];
#pragma unroll
        for (int mt = 0; mt < 4; ++mt) {
            const __nv_bfloat16 *p = As + (wm * 64 + mt * 16 + gid) * LDA + k0 + 2 * tig;
            a[mt][0] = *(const u32 *)p;
            a[mt][1] = *(const u32 *)(p + 8 * LDA);
            a[mt][2] = *(const u32 *)(p + 8);
            a[mt][3] = *(const u32 *)(p + 8 * LDA + 8);
        }
#pragma unroll
        for (int nt = 0; nt < 4; ++nt) {
            const __nv_bfloat16 *p = Bs + (wn * 32 + nt * 8 + gid) * LDA + k0 + 2 * tig;
            b[nt][0] = *(const u32 *)p;
            b[nt][1] = *(const u32 *)(p + 8);
        }
#pragma unroll
        for (int mt = 0; mt < 4; ++mt)
#pragma unroll
            for (int nt = 0; nt < 4; ++nt) mma16816(acc[mt][nt], a[mt], b[nt]);
    }

    // epilogue: + bias, -> bf16, store
    float bb0[4], bb1[4];
#pragma unroll
    for (int nt = 0; nt < 4; ++nt) {
        int n = g0 + wn * 32 + nt * 8 + 2 * tig;
        bb0[nt] = bih1[n] + bhh1[n];
        bb1[nt] = bih1[n + 1] + bhh1[n + 1];
    }
#pragma unroll
    for (int mt = 0; mt < 4; ++mt) {
        size_t row0 = bt0 + wm * 64 + mt * 16 + gid;
#pragma unroll
        for (int nt = 0; nt < 4; ++nt) {
            int n = g0 + wn * 32 + nt * 8 + 2 * tig;
            __nv_bfloat162 v0 = __floats2bfloat162_rn(acc[mt][nt][0] + bb0[nt], acc[mt][nt][1] + bb1[nt]);
            __nv_bfloat162 v1 = __floats2bfloat162_rn(acc[mt][nt][2] + bb0[nt], acc[mt][nt][3] + bb1[nt]);
            *reinterpret_cast<__nv_bfloat162 *>(g_xg1 + row0 * GG + n) = v0;
            *reinterpret_cast<__nv_bfloat162 *>(g_xg1 + (row0 + 8) * GG + n) = v1;
        }
    }
}

// ---------------- K2: layer-1 LSTM (xg pre-computed). 128 blocks x 1024 threads ----------------
extern "C" __global__ void __launch_bounds__(1024, 1)
k_lstm1(const float *__restrict__ Whh1) {
    extern __shared__ char smem[];
    uint2 *Ws = (uint2 *)smem;                       // 131072 B
    float *hs = (float *)(smem + 131072);            // 2048 B
    float *stage = (float *)(smem + 133120);         // 16384 B [2][4][512]
    const int tid = threadIdx.x;
    const int rb = blockIdx.x * ROWS;
    const int g = tid & (GG - 1);
    const int kh = tid >> 9;
    const int r = (tid >> 7) & 3, j = tid & (HH - 1);

    load_w(Ws, Whh1, tid, 1024);
    if (tid < 512) hs[tid] = 0.f;
    float c = 0.f;
    __syncthreads();

    const __nv_bfloat16 *xg = g_xg1 + ((size_t)(rb + r) * TT) * GG + j;
#pragma unroll 1
    for (int t = 0; t < TT; ++t) {
        float xi = 0.f, xf = 0.f, xgg = 0.f, xo = 0.f;
        if (tid < 512) {  // prefetch; ~600cyc gmem latency hides under the dot
            const __nv_bfloat16 *xp = xg + (size_t)t * GG;
            xi = __bfloat162float(xp[0]);
            xf = __bfloat162float(xp[HH]);
            xgg = __bfloat162float(xp[2 * HH]);
            xo = __bfloat162float(xp[3 * HH]);
        }
        float d[4];
        dot4h(Ws, hs, g, kh * 16, d);
        float *st = stage + kh * 2048 + g;
        st[0 * GG] = d[0];
        st[1 * GG] = d[1];
        st[2 * GG] = d[2];
        st[3 * GG] = d[3];
        __syncthreads();
        if (tid < 512) {
            const float *s0 = stage + r * GG;
            const float *s1 = stage + 2048 + r * GG;
            float gi = s0[j] + s1[j] + xi;
            float gf = s0[j + HH] + s1[j + HH] + xf;
            float gg = s0[j + 2 * HH] + s1[j + 2 * HH] + xgg;
            float go = s0[j + 3 * HH] + s1[j + 3 * HH] + xo;
            c = sigm(gf) * c + sigm(gi) * tanha(gg);
            float h = sigm(go) * tanha(c);
            hs[tid] = h;
            if (t == TT - 1) g_h1f[(rb + r) * HH + j] = h;
        }
        __syncthreads();
    }
}

// ---------------- K3: classifier MLP + double softmax ----------------
extern "C" __global__ void __launch_bounds__(128)
k_cls(const float *__restrict__ W1, const float *__restrict__ b1,
      const float *__restrict__ W2, const float *__restrict__ b2,
      const float *__restrict__ W3, const float *__restrict__ b3,
      float *__restrict__ out) {
    __shared__ float hb[128], z1[128], z2[64], z3[8];
    const int tid = threadIdx.x;
    const int row = blockIdx.x;
    hb[tid] = g_h1f[row * HH + tid];
    __syncthreads();
    float a = b1[tid];
#pragma unroll 4
    for (int k = 0; k < 128; ++k) a = fmaf(W1[tid * 128 + k], hb[k], a);
    z1[tid] = fmaxf(a, 0.f);
    __syncthreads();
    if (tid < 64) {
        float s = b2[tid];
#pragma unroll 4
        for (int k = 0; k < 128; ++k) s = fmaf(W2[tid * 128 + k], z1[k], s);
        z2[tid] = fmaxf(s, 0.f);
    }
    __syncthreads();
    if (tid < 6) {
        float s = b3[tid];
#pragma unroll 4
        for (int k = 0; k < 64; ++k) s = fmaf(W3[tid * 64 + k], z2[k], s);
        z3[tid] = s;
    }
    __syncthreads();
    if (tid == 0) {
        float v[6];
#pragma unroll
        for (int i = 0; i < 6; ++i) v[i] = z3[i];
#pragma unroll
        for (int p = 0; p < 2; ++p) {
            float m = v[0];
            for (int i = 1; i < 6; ++i) m = fmaxf(m, v[i]);
            float s = 0.f;
            for (int i = 0; i < 6; ++i) { v[i] = expf(v[i] - m); s += v[i]; }
            float inv = 1.f / s;
            for (int i = 0; i < 6; ++i) v[i] *= inv;
        }
        for (int i = 0; i < 6; ++i) out[row * 6 + i] = v[i];
    }
}

extern "C" void kernel_launch(void *const *d_in, const int *in_sizes, int n_in,
                              void *d_out, int out_size) {
    const float *x = (const float *)d_in[0];
    const float *Wih0 = (const float *)d_in[1];
    const float *Whh0 = (const float *)d_in[2];
    const float *bih0 = (const float *)d_in[3];
    const float *bhh0 = (const float *)d_in[4];
    const float *Wih1 = (const float *)d_in[5];
    const float *Whh1 = (const float *)d_in[6];
    const float *bih1 = (const float *)d_in[7];
    const float *bhh1 = (const float *)d_in[8];
    const float *W1 = (const float *)d_in[9];
    const float *b1 = (const float *)d_in[10];
    const float *W2 = (const float *)d_in[11];
    const float *b2 = (const float *)d_in[12];
    const float *W3 = (const float *)d_in[13];
    const float *b3 = (const float *)d_in[14];
    float *out = (float *)d_out;

    const int SMEM0 = 131072 + 65536 + 2048 + 16384 + 4096 + 2048;  // 221184
    const int SMEM1 = 2 * 128 * LDA * 2;                            // 69632
    const int SMEM2 = 131072 + 2048 + 16384;                        // 149504
    cudaFuncSetAttribute(k_lstm0, cudaFuncAttributeMaxDynamicSharedMemorySize, SMEM0);
    cudaFuncSetAttribute(k_gemm1, cudaFuncAttributeMaxDynamicSharedMemorySize, SMEM1);
    cudaFuncSetAttribute(k_lstm1, cudaFuncAttributeMaxDynamicSharedMemorySize, SMEM2);

    k_lstm0<<<BB / ROWS, 1024, SMEM0>>>(x, Wih0, Whh0, bih0, bhh0);
    k_gemm1<<<dim3((BB * TT) / 128, GG / 128), 256, SMEM1>>>(Wih1, bih1, bhh1);
    k_lstm1<<<BB / ROWS, 1024, SMEM2>>>(Whh1);
    k_cls<<<BB, 128>>>(W1, b1, W2, b2, W3, b3, out);
}

// round 5
// speedup vs baseline: 3.7649x; 2.4471x over previous
#include <cuda_runtime.h>
#include <cuda_bf16.h>
#include <math.h>

#define TT 2048
#define BB 512
#define HH 128
#define GG 512
#define ROWS 8          // batch rows per block (m16 tile half-used)
#define NBLK (BB / ROWS)
#define PADH0 152       // layer-0 h row stride (bf16): 128 h + fx,fy,1 + pad, conflict-free
#define PADH1 136       // layer-1 h row stride

typedef unsigned long long u64;
typedef unsigned int u32;

// scratch (static device globals: allowed; no cudaMalloc anywhere)
static __device__ __nv_bfloat16 g_y0[(size_t)BB * TT * HH];   // layer-0 outputs (bf16)
static __device__ __nv_bfloat16 g_xg1[(size_t)BB * TT * GG];  // layer-1 input gates + bias (bf16)
static __device__ float g_h1f[BB * HH];                       // final hidden of layer 1

__device__ __forceinline__ float tanha(float x) {
    asm("tanh.approx.f32 %0, %0;" : "+f"(x));
    return x;
}
__device__ __forceinline__ float sigm(float x) { return fmaf(tanha(0.5f * x), 0.5f, 0.5f); }

__device__ __forceinline__ u32 pbf2(float a, float b) {
    __nv_bfloat162 t = __floats2bfloat162_rn(a, b);
    return *(u32 *)&t;
}
__device__ __forceinline__ float bflo(u32 u) { return __uint_as_float(u << 16); }
__device__ __forceinline__ float bfhi(u32 u) { return __uint_as_float(u & 0xffff0000u); }

__device__ __forceinline__ void mma16816(float *c, const u32 *a, const u32 *b) {
    asm volatile(
        "mma.sync.aligned.m16n8k16.row.col.f32.bf16.bf16.f32 "
        "{%0,%1,%2,%3}, {%4,%5,%6,%7}, {%8,%9}, {%0,%1,%2,%3};"
        : "+f"(c[0]), "+f"(c[1]), "+f"(c[2]), "+f"(c[3])
        : "r"(a[0]), "r"(a[1]), "r"(a[2]), "r"(a[3]), "r"(b[0]), "r"(b[1]));
}

// ================= K0: layer-0 LSTM, HMMA recurrence, input term folded as k-tile 8 =================
// 64 blocks x 256 threads. Warp w owns units [w*16, w*16+16). Whh+Wih+bias in registers (B frags).
extern "C" __global__ void __launch_bounds__(256, 1)
k_lstm0(const float *__restrict__ x, const float *__restrict__ Wih0,
        const float *__restrict__ Whh0, const float *__restrict__ bih0,
        const float *__restrict__ bhh0) {
    __shared__ __nv_bfloat16 hbuf[2][16 * PADH0];
    const int tid = threadIdx.x;
    const int w = tid >> 5, lane = tid & 31, gid = lane >> 2, tig = lane & 3;
    const int rb = blockIdx.x * ROWS;

    // ---- B fragments in registers: nt = gate*2+half ----
    u32 b[8][8][2];   // k-tiles 0..7: Whh
    u32 b8lo[8];      // k-tile 8 reg0: (Wih pair | bias | 0)
#pragma unroll
    for (int g = 0; g < 4; ++g)
#pragma unroll
        for (int half = 0; half < 2; ++half) {
            const int nt = g * 2 + half;
            const int gr = g * 128 + w * 16 + half * 8 + gid;  // B n-index uses gid
#pragma unroll
            for (int kt = 0; kt < 8; ++kt) {
                const int k = kt * 16 + 2 * tig;
                float2 w0 = *reinterpret_cast<const float2 *>(Whh0 + (size_t)gr * HH + k);
                float2 w1 = *reinterpret_cast<const float2 *>(Whh0 + (size_t)gr * HH + k + 8);
                b[nt][kt][0] = pbf2(w0.x, w0.y);
                b[nt][kt][1] = pbf2(w1.x, w1.y);
            }
            u32 lo = 0;
            if (tig == 0) lo = pbf2(Wih0[gr * 2], Wih0[gr * 2 + 1]);        // k=128,129
            else if (tig == 1) lo = pbf2(bih0[gr] + bhh0[gr], 0.f);          // k=130,131
            b8lo[nt] = lo;
        }

    // ---- init h buffers: zeros; col 130 = 1.0 (both buffers); feats(t=0) in buf0 ----
    for (int i = tid; i < 2 * 16 * PADH0 / 2; i += 256) ((u32 *)hbuf)[i] = 0;
    __syncthreads();
    if (tid < ROWS) {
        const float *xp = x + ((size_t)(rb + tid) * TT) * 6;
        float fx = sqrtf(xp[0] * xp[0] + xp[1] * xp[1] + xp[2] * xp[2]);
        float fy = sqrtf(xp[3] * xp[3] + xp[4] * xp[4] + xp[5] * xp[5]);
        *(u32 *)&hbuf[0][tid * PADH0 + 128] = pbf2(fx, fy);
        *(u32 *)&hbuf[0][tid * PADH0 + 130] = pbf2(1.f, 0.f);
        *(u32 *)&hbuf[1][tid * PADH0 + 130] = pbf2(1.f, 0.f);
    }
    __syncthreads();

    float cst[4] = {0.f, 0.f, 0.f, 0.f};
    const int j0a = w * 16 + 2 * tig;       // half 0 col pair base (C n-index uses 2*tig)
    const int j0b = w * 16 + 8 + 2 * tig;   // half 1

#pragma unroll 1
    for (int t = 0; t < TT; ++t) {
        const __nv_bfloat16 *hb = hbuf[t & 1];
        // prefetch feats(t+1) — hides under the MMA phase
        float pfx = 0.f, pfy = 0.f;
        if (tid < ROWS && t + 1 < TT) {
            const float *xp = x + ((size_t)(rb + tid) * TT + (t + 1)) * 6;
            pfx = sqrtf(xp[0] * xp[0] + xp[1] * xp[1] + xp[2] * xp[2]);
            pfy = sqrtf(xp[3] * xp[3] + xp[4] * xp[4] + xp[5] * xp[5]);
        }
        // A fragments
        u32 a[9][4];
#pragma unroll
        for (int kt = 0; kt < 9; ++kt) {
            const int base = gid * PADH0 + kt * 16 + 2 * tig;
            a[kt][0] = *(const u32 *)&hb[base];
            a[kt][1] = *(const u32 *)&hb[base + 8 * PADH0];
            a[kt][2] = *(const u32 *)&hb[base + 8];
            a[kt][3] = *(const u32 *)&hb[base + 8 * PADH0 + 8];
        }
        float acc[8][4];
#pragma unroll
        for (int nt = 0; nt < 8; ++nt) { acc[nt][0] = acc[nt][1] = acc[nt][2] = acc[nt][3] = 0.f; }
#pragma unroll
        for (int kt = 0; kt < 8; ++kt)
#pragma unroll
            for (int nt = 0; nt < 8; ++nt) mma16816(acc[nt], a[kt], b[nt][kt]);
        {
            u32 bz = 0;
#pragma unroll
            for (int nt = 0; nt < 8; ++nt) {
                u32 b8[2] = {b8lo[nt], bz};
                mma16816(acc[nt], a[8], b8);
            }
        }
        // pointwise (valid rows = gid, slots s=0,1) + h store + y0 store
        __nv_bfloat16 *hn = hbuf[(t + 1) & 1];
        __nv_bfloat16 *yrow = g_y0 + (((size_t)(rb + gid)) * TT + t) * HH;
#pragma unroll
        for (int half = 0; half < 2; ++half) {
            float hh[2];
#pragma unroll
            for (int s = 0; s < 2; ++s) {
                float &cs = cst[half * 2 + s];
                cs = sigm(acc[2 + half][s]) * cs + sigm(acc[half][s]) * tanha(acc[4 + half][s]);
                hh[s] = sigm(acc[6 + half][s]) * tanha(cs);
            }
            const u32 hp = pbf2(hh[0], hh[1]);
            const int j0 = half ? j0b : j0a;
            *(u32 *)&hn[gid * PADH0 + j0] = hp;
            *(u32 *)&yrow[j0] = hp;
        }
        if (tid < ROWS && t + 1 < TT) *(u32 *)&hn[tid * PADH0 + 128] = pbf2(pfx, pfy);
        __syncthreads();
    }
}

// ================= K1: xg1 = y0 @ Wih1^T + bias, bf16 HMMA (unchanged from R3) =================
#define LDA 136
extern "C" __global__ void __launch_bounds__(256)
k_gemm1(const float *__restrict__ Wih1, const float *__restrict__ bih1,
        const float *__restrict__ bhh1) {
    extern __shared__ char smem[];
    __nv_bfloat16 *As = (__nv_bfloat16 *)smem;
    __nv_bfloat16 *Bs = As + 128 * LDA;
    const int tid = threadIdx.x;
    const size_t bt0 = (size_t)blockIdx.x * 128;
    const int g0 = blockIdx.y * 128;

    for (int v = tid; v < 128 * 16; v += 256) {
        int m = v >> 4, kc = v & 15;
        uint4 raw = *reinterpret_cast<const uint4 *>(g_y0 + (bt0 + m) * HH + kc * 8);
        *reinterpret_cast<uint4 *>(As + m * LDA + kc * 8) = raw;
    }
    for (int v = tid; v < 128 * 32; v += 256) {
        int gl = v >> 5, kc = v & 31;
        float4 wv = *reinterpret_cast<const float4 *>(Wih1 + (size_t)(g0 + gl) * HH + kc * 4);
        *reinterpret_cast<__nv_bfloat162 *>(Bs + gl * LDA + kc * 4) = __floats2bfloat162_rn(wv.x, wv.y);
        *reinterpret_cast<__nv_bfloat162 *>(Bs + gl * LDA + kc * 4 + 2) = __floats2bfloat162_rn(wv.z, wv.w);
    }
    __syncthreads();

    const int w = tid >> 5, lane = tid & 31, gid = lane >> 2, tig = lane & 3;
    const int wm = w & 1, wn = w >> 1;
    float acc[4][4][4];
#pragma unroll
    for (int mt = 0; mt < 4; ++mt)
#pragma unroll
        for (int nt = 0; nt < 4; ++nt)
#pragma unroll
            for (int i = 0; i < 4; ++i) acc[mt][nt][i] = 0.f;

#pragma unroll
    for (int ks = 0; ks < 8; ++ks) {
        const int k0 = ks * 16;
        u32 a[4][4], b[4][2];
#pragma unroll
        for (int mt = 0; mt < 4; ++mt) {
            const __nv_bfloat16 *p = As + (wm * 64 + mt * 16 + gid) * LDA + k0 + 2 * tig;
            a[mt][0] = *(const u32 *)p;
            a[mt][1] = *(const u32 *)(p + 8 * LDA);
            a[mt][2] = *(const u32 *)(p + 8);
            a[mt][3] = *(const u32 *)(p + 8 * LDA + 8);
        }
#pragma unroll
        for (int nt = 0; nt < 4; ++nt) {
            const __nv_bfloat16 *p = Bs + (wn * 32 + nt * 8 + gid) * LDA + k0 + 2 * tig;
            b[nt][0] = *(const u32 *)p;
            b[nt][1] = *(const u32 *)(p + 8);
        }
#pragma unroll
        for (int mt = 0; mt < 4; ++mt)
#pragma unroll
            for (int nt = 0; nt < 4; ++nt) mma16816(acc[mt][nt], a[mt], b[nt]);
    }
    float bb0[4], bb1[4];
#pragma unroll
    for (int nt = 0; nt < 4; ++nt) {
        int n = g0 + wn * 32 + nt * 8 + 2 * tig;
        bb0[nt] = bih1[n] + bhh1[n];
        bb1[nt] = bih1[n + 1] + bhh1[n + 1];
    }
#pragma unroll
    for (int mt = 0; mt < 4; ++mt) {
        size_t row0 = bt0 + wm * 64 + mt * 16 + gid;
#pragma unroll
        for (int nt = 0; nt < 4; ++nt) {
            int n = g0 + wn * 32 + nt * 8 + 2 * tig;
            *reinterpret_cast<__nv_bfloat162 *>(g_xg1 + row0 * GG + n) =
                __floats2bfloat162_rn(acc[mt][nt][0] + bb0[nt], acc[mt][nt][1] + bb1[nt]);
            *reinterpret_cast<__nv_bfloat162 *>(g_xg1 + (row0 + 8) * GG + n) =
                __floats2bfloat162_rn(acc[mt][nt][2] + bb0[nt], acc[mt][nt][3] + bb1[nt]);
        }
    }
}

// ================= K2: layer-1 LSTM, HMMA recurrence, xg from gmem =================
extern "C" __global__ void __launch_bounds__(256, 1)
k_lstm1(const float *__restrict__ Whh1) {
    __shared__ __nv_bfloat16 hbuf[2][16 * PADH1];
    const int tid = threadIdx.x;
    const int w = tid >> 5, lane = tid & 31, gid = lane >> 2, tig = lane & 3;
    const int rb = blockIdx.x * ROWS;

    u32 b[8][8][2];
    int gcol[8];  // xg column per nt (C n-index: 2*tig)
#pragma unroll
    for (int g = 0; g < 4; ++g)
#pragma unroll
        for (int half = 0; half < 2; ++half) {
            const int nt = g * 2 + half;
            const int gr = g * 128 + w * 16 + half * 8 + gid;
            gcol[nt] = g * 128 + w * 16 + half * 8 + 2 * tig;
#pragma unroll
            for (int kt = 0; kt < 8; ++kt) {
                const int k = kt * 16 + 2 * tig;
                float2 w0 = *reinterpret_cast<const float2 *>(Whh1 + (size_t)gr * HH + k);
                float2 w1 = *reinterpret_cast<const float2 *>(Whh1 + (size_t)gr * HH + k + 8);
                b[nt][kt][0] = pbf2(w0.x, w0.y);
                b[nt][kt][1] = pbf2(w1.x, w1.y);
            }
        }

    for (int i = tid; i < 2 * 16 * PADH1 / 2; i += 256) ((u32 *)hbuf)[i] = 0;
    __syncthreads();

    float cst[4] = {0.f, 0.f, 0.f, 0.f};
    const __nv_bfloat16 *xgbase = g_xg1 + ((size_t)(rb + gid) * TT) * GG;
    const int j0a = w * 16 + 2 * tig;
    const int j0b = w * 16 + 8 + 2 * tig;

#pragma unroll 1
    for (int t = 0; t < TT; ++t) {
        // prefetch this step's input-gate values (consumed after the MMA phase)
        u32 xgv[8];
        const __nv_bfloat16 *xp = xgbase + (size_t)t * GG;
#pragma unroll
        for (int nt = 0; nt < 8; ++nt) xgv[nt] = *(const u32 *)&xp[gcol[nt]];

        const __nv_bfloat16 *hb = hbuf[t & 1];
        u32 a[8][4];
#pragma unroll
        for (int kt = 0; kt < 8; ++kt) {
            const int base = gid * PADH1 + kt * 16 + 2 * tig;
            a[kt][0] = *(const u32 *)&hb[base];
            a[kt][1] = *(const u32 *)&hb[base + 8 * PADH1];
            a[kt][2] = *(const u32 *)&hb[base + 8];
            a[kt][3] = *(const u32 *)&hb[base + 8 * PADH1 + 8];
        }
        float acc[8][4];
#pragma unroll
        for (int nt = 0; nt < 8; ++nt) { acc[nt][0] = acc[nt][1] = acc[nt][2] = acc[nt][3] = 0.f; }
#pragma unroll
        for (int kt = 0; kt < 8; ++kt)
#pragma unroll
            for (int nt = 0; nt < 8; ++nt) mma16816(acc[nt], a[kt], b[nt][kt]);
#pragma unroll
        for (int nt = 0; nt < 8; ++nt) {
            acc[nt][0] += bflo(xgv[nt]);
            acc[nt][1] += bfhi(xgv[nt]);
        }
        __nv_bfloat16 *hn = hbuf[(t + 1) & 1];
#pragma unroll
        for (int half = 0; half < 2; ++half) {
            float hh[2];
#pragma unroll
            for (int s = 0; s < 2; ++s) {
                float &cs = cst[half * 2 + s];
                cs = sigm(acc[2 + half][s]) * cs + sigm(acc[half][s]) * tanha(acc[4 + half][s]);
                hh[s] = sigm(acc[6 + half][s]) * tanha(cs);
            }
            const int j0 = half ? j0b : j0a;
            *(u32 *)&hn[gid * PADH1 + j0] = pbf2(hh[0], hh[1]);
            if (t == TT - 1) {
                g_h1f[(rb + gid) * HH + j0] = hh[0];
                g_h1f[(rb + gid) * HH + j0 + 1] = hh[1];
            }
        }
        __syncthreads();
    }
}

// ================= K3: classifier MLP + double softmax =================
extern "C" __global__ void __launch_bounds__(128)
k_cls(const float *__restrict__ W1, const float *__restrict__ b1,
      const float *__restrict__ W2, const float *__restrict__ b2,
      const float *__restrict__ W3, const float *__restrict__ b3,
      float *__restrict__ out) {
    __shared__ float hb[128], z1[128], z2[64], z3[8];
    const int tid = threadIdx.x;
    const int row = blockIdx.x;
    hb[tid] = g_h1f[row * HH + tid];
    __syncthreads();
    float a = b1[tid];
#pragma unroll 4
    for (int k = 0; k < 128; ++k) a = fmaf(W1[tid * 128 + k], hb[k], a);
    z1[tid] = fmaxf(a, 0.f);
    __syncthreads();
    if (tid < 64) {
        float s = b2[tid];
#pragma unroll 4
        for (int k = 0; k < 128; ++k) s = fmaf(W2[tid * 128 + k], z1[k], s);
        z2[tid] = fmaxf(s, 0.f);
    }
    __syncthreads();
    if (tid < 6) {
        float s = b3[tid];
#pragma unroll 4
        for (int k = 0; k < 64; ++k) s = fmaf(W3[tid * 64 + k], z2[k], s);
        z3[tid] = s;
    }
    __syncthreads();
    if (tid == 0) {
        float v[6];
#pragma unroll
        for (int i = 0; i < 6; ++i) v[i] = z3[i];
#pragma unroll
        for (int p = 0; p < 2; ++p) {
            float m = v[0];
            for (int i = 1; i < 6; ++i) m = fmaxf(m, v[i]);
            float s = 0.f;
            for (int i = 0; i < 6; ++i) { v[i] = expf(v[i] - m); s += v[i]; }
            float inv = 1.f / s;
            for (int i = 0; i < 6; ++i) v[i] *= inv;
        }
        for (int i = 0; i < 6; ++i) out[row * 6 + i] = v[i];
    }
}

extern "C" void kernel_launch(void *const *d_in, const int *in_sizes, int n_in,
                              void *d_out, int out_size) {
    const float *x = (const float *)d_in[0];
    const float *Wih0 = (const float *)d_in[1];
    const float *Whh0 = (const float *)d_in[2];
    const float *bih0 = (const float *)d_in[3];
    const float *bhh0 = (const float *)d_in[4];
    const float *Wih1 = (const float *)d_in[5];
    const float *Whh1 = (const float *)d_in[6];
    const float *bih1 = (const float *)d_in[7];
    const float *bhh1 = (const float *)d_in[8];
    const float *W1 = (const float *)d_in[9];
    const float *b1 = (const float *)d_in[10];
    const float *W2 = (const float *)d_in[11];
    const float *b2 = (const float *)d_in[12];
    const float *W3 = (const float *)d_in[13];
    const float *b3 = (const float *)d_in[14];
    float *out = (float *)d_out;

    const int SMEM1 = 2 * 128 * LDA * 2;  // 69632
    cudaFuncSetAttribute(k_gemm1, cudaFuncAttributeMaxDynamicSharedMemorySize, SMEM1);

    k_lstm0<<<NBLK, 256>>>(x, Wih0, Whh0, bih0, bhh0);
    k_gemm1<<<dim3((BB * TT) / 128, GG / 128), 256, SMEM1>>>(Wih1, bih1, bhh1);
    k_lstm1<<<NBLK, 256>>>(Whh1);
    k_cls<<<BB, 128>>>(W1, b1, W2, b2, W3, b3, out);
}

// round 6
// speedup vs baseline: 4.9778x; 1.3222x over previous
#include <cuda_runtime.h>
#include <cuda_bf16.h>
#include <math.h>

#define TT 2048
#define BB 512
#define HH 128
#define GG 512
#define ROWS 8
#define NBLK (BB / ROWS)
#define PADH 136    // h row stride per batch row (bf16) — conflict-free B-frag loads
#define FPAD 2052   // feats row stride (u32) — conflict-free per-gid reads
#define XPAD 520    // xg row stride (bf16) — conflict-free pointwise reads

typedef unsigned long long u64;
typedef unsigned int u32;

// scratch (static device globals: allowed; no cudaMalloc anywhere)
static __device__ __nv_bfloat16 g_y0[(size_t)BB * TT * HH];   // layer-0 outputs (bf16)
static __device__ __nv_bfloat16 g_xg1[(size_t)BB * TT * GG];  // layer-1 input gates + bias (bf16)
static __device__ float g_h1f[BB * HH];                       // final hidden of layer 1

__device__ __forceinline__ float tanha(float x) {
    asm("tanh.approx.f32 %0, %0;" : "+f"(x));
    return x;
}
__device__ __forceinline__ float sigm(float x) { return fmaf(tanha(0.5f * x), 0.5f, 0.5f); }

__device__ __forceinline__ u32 pbf2(float a, float b) {
    __nv_bfloat162 t = __floats2bfloat162_rn(a, b);
    return *(u32 *)&t;
}

__device__ __forceinline__ void mma16816(float *c, const u32 *a, const u32 *b) {
    asm volatile(
        "mma.sync.aligned.m16n8k16.row.col.f32.bf16.bf16.f32 "
        "{%0,%1,%2,%3}, {%4,%5,%6,%7}, {%8,%9}, {%0,%1,%2,%3};"
        : "+f"(c[0]), "+f"(c[1]), "+f"(c[2]), "+f"(c[3])
        : "r"(a[0]), "r"(a[1]), "r"(a[2]), "r"(a[3]), "r"(b[0]), "r"(b[1]));
}

// ================= K0: layer-0 LSTM, transposed HMMA recurrence (gates on m, batch on n=8) ========
// 64 blocks x 256 threads. Warp w owns units [w*16, w*16+16). Whh+Wih+bias in A-register fragments.
extern "C" __global__ void __launch_bounds__(256, 1)
k_lstm0(const float *__restrict__ x, const float *__restrict__ Wih0,
        const float *__restrict__ Whh0, const float *__restrict__ bih0,
        const float *__restrict__ bhh0) {
    extern __shared__ char smem[];
    u32 *feats = (u32 *)smem;                                   // [8][FPAD]  65664 B
    __nv_bfloat16 *hbuf = (__nv_bfloat16 *)(smem + 8 * FPAD * 4);  // [2][8][PADH] 4352 B
    const int tid = threadIdx.x;
    const int w = tid >> 5, lane = tid & 31, gid = lane >> 2, tig = lane & 3;
    const int rb = blockIdx.x * ROWS;
    const int u0 = w * 16 + gid, u1 = u0 + 8;
    const int r0 = 2 * tig, r1 = r0 + 1;

    // A fragments (row-major, m = gate rows): a0=A[gid,k..k+1] a1=A[gid+8] a2=A[gid,k+8..] a3=A[gid+8,k+8..]
    u32 a[4][8][4];
#pragma unroll
    for (int g = 0; g < 4; ++g) {
        const int gr0 = g * 128 + u0, gr1 = g * 128 + u1;
#pragma unroll
        for (int kt = 0; kt < 8; ++kt) {
            const int k = kt * 16 + 2 * tig;
            a[g][kt][0] = pbf2(Whh0[(size_t)gr0 * HH + k], Whh0[(size_t)gr0 * HH + k + 1]);
            a[g][kt][1] = pbf2(Whh0[(size_t)gr1 * HH + k], Whh0[(size_t)gr1 * HH + k + 1]);
            a[g][kt][2] = pbf2(Whh0[(size_t)gr0 * HH + k + 8], Whh0[(size_t)gr0 * HH + k + 9]);
            a[g][kt][3] = pbf2(Whh0[(size_t)gr1 * HH + k + 8], Whh0[(size_t)gr1 * HH + k + 9]);
        }
    }
    // fold k-tile: cols 128,129 = Wih, col 130 = bias (x "1")
    u32 af0[4], af1[4];
#pragma unroll
    for (int g = 0; g < 4; ++g) {
        const int gr0 = g * 128 + u0, gr1 = g * 128 + u1;
        af0[g] = (tig == 0) ? pbf2(Wih0[gr0 * 2], Wih0[gr0 * 2 + 1])
                            : (tig == 1 ? pbf2(bih0[gr0] + bhh0[gr0], 0.f) : 0u);
        af1[g] = (tig == 0) ? pbf2(Wih0[gr1 * 2], Wih0[gr1 * 2 + 1])
                            : (tig == 1 ? pbf2(bih0[gr1] + bhh0[gr1], 0.f) : 0u);
    }

    // precompute feature norms for all 8 rows x 2048 t (bf16 pairs)
    for (int i = tid; i < ROWS * TT; i += 256) {
        int r = i >> 11, t = i & (TT - 1);
        const float *xp = x + ((size_t)(rb + r) * TT + t) * 6;
        float fx = sqrtf(xp[0] * xp[0] + xp[1] * xp[1] + xp[2] * xp[2]);
        float fy = sqrtf(xp[3] * xp[3] + xp[4] * xp[4] + xp[5] * xp[5]);
        feats[r * FPAD + t] = pbf2(fx, fy);
    }
    for (int i = tid; i < 2 * ROWS * PADH / 2; i += 256) ((u32 *)hbuf)[i] = 0u;
    const u32 bfc = (tig == 1) ? pbf2(1.f, 0.f) : 0u;
    float c[4] = {0.f, 0.f, 0.f, 0.f};
    __syncthreads();

#pragma unroll 1
    for (int t = 0; t < TT; ++t) {
        const __nv_bfloat16 *hb = hbuf + (t & 1) * ROWS * PADH;
        __nv_bfloat16 *hn = hbuf + ((t + 1) & 1) * ROWS * PADH;
        // B fragments: B[k, n=batch] — hb[batch][k], k-contiguous
        u32 b[8][2];
#pragma unroll
        for (int kt = 0; kt < 8; ++kt) {
            const int base = gid * PADH + kt * 16 + 2 * tig;
            b[kt][0] = *(const u32 *)&hb[base];
            b[kt][1] = *(const u32 *)&hb[base + 8];
        }
        u32 bf0 = (tig == 0) ? feats[gid * FPAD + t] : bfc;
        float acc[4][4];
#pragma unroll
        for (int g = 0; g < 4; ++g) { acc[g][0] = acc[g][1] = acc[g][2] = acc[g][3] = 0.f; }
#pragma unroll
        for (int kt = 0; kt < 8; ++kt)
#pragma unroll
            for (int g = 0; g < 4; ++g) mma16816(acc[g], a[g][kt], b[kt]);
#pragma unroll
        for (int g = 0; g < 4; ++g) {
            u32 afr[4] = {af0[g], af1[g], 0u, 0u};
            u32 bfr[2] = {bf0, 0u};
            mma16816(acc[g], afr, bfr);
        }
        // pointwise: slots s: 0=(u0,r0) 1=(u0,r1) 2=(u1,r0) 3=(u1,r1); gates acc[0..3]=i,f,g,o
        float h[4];
#pragma unroll
        for (int s = 0; s < 4; ++s) {
            c[s] = sigm(acc[1][s]) * c[s] + sigm(acc[0][s]) * tanha(acc[2][s]);
            h[s] = sigm(acc[3][s]) * tanha(c[s]);
        }
        hn[r0 * PADH + u0] = __float2bfloat16(h[0]);
        hn[r1 * PADH + u0] = __float2bfloat16(h[1]);
        hn[r0 * PADH + u1] = __float2bfloat16(h[2]);
        hn[r1 * PADH + u1] = __float2bfloat16(h[3]);
        __syncthreads();
        // coalesced y0 store from the completed h tile
        if (tid < 128) {
            int row = tid >> 4, q = tid & 15;
            uint4 v = *(const uint4 *)&hn[row * PADH + q * 8];
            *(uint4 *)(g_y0 + ((size_t)(rb + row) * TT + t) * HH + q * 8) = v;
        }
    }
}

// ================= K1: xg1 = y0 @ Wih1^T + bias, bf16 HMMA (validated in R3/R4) =================
#define LDA 136
extern "C" __global__ void __launch_bounds__(256, 2)
k_gemm1(const float *__restrict__ Wih1, const float *__restrict__ bih1,
        const float *__restrict__ bhh1) {
    extern __shared__ char smem[];
    __nv_bfloat16 *As = (__nv_bfloat16 *)smem;
    __nv_bfloat16 *Bs = As + 128 * LDA;
    const int tid = threadIdx.x;
    const size_t bt0 = (size_t)blockIdx.x * 128;
    const int g0 = blockIdx.y * 128;

    for (int v = tid; v < 128 * 16; v += 256) {
        int m = v >> 4, kc = v & 15;
        uint4 raw = *reinterpret_cast<const uint4 *>(g_y0 + (bt0 + m) * HH + kc * 8);
        *reinterpret_cast<uint4 *>(As + m * LDA + kc * 8) = raw;
    }
    for (int v = tid; v < 128 * 32; v += 256) {
        int gl = v >> 5, kc = v & 31;
        float4 wv = *reinterpret_cast<const float4 *>(Wih1 + (size_t)(g0 + gl) * HH + kc * 4);
        *reinterpret_cast<__nv_bfloat162 *>(Bs + gl * LDA + kc * 4) = __floats2bfloat162_rn(wv.x, wv.y);
        *reinterpret_cast<__nv_bfloat162 *>(Bs + gl * LDA + kc * 4 + 2) = __floats2bfloat162_rn(wv.z, wv.w);
    }
    __syncthreads();

    const int w = tid >> 5, lane = tid & 31, gid = lane >> 2, tig = lane & 3;
    const int wm = w & 1, wn = w >> 1;
    float acc[4][4][4];
#pragma unroll
    for (int mt = 0; mt < 4; ++mt)
#pragma unroll
        for (int nt = 0; nt < 4; ++nt)
#pragma unroll
            for (int i = 0; i < 4; ++i) acc[mt][nt][i] = 0.f;

#pragma unroll
    for (int ks = 0; ks < 8; ++ks) {
        const int k0 = ks * 16;
        u32 a[4][4], b[4][2];
#pragma unroll
        for (int mt = 0; mt < 4; ++mt) {
            const __nv_bfloat16 *p = As + (wm * 64 + mt * 16 + gid) * LDA + k0 + 2 * tig;
            a[mt][0] = *(const u32 *)p;
            a[mt][1] = *(const u32 *)(p + 8 * LDA);
            a[mt][2] = *(const u32 *)(p + 8);
            a[mt][3] = *(const u32 *)(p + 8 * LDA + 8);
        }
#pragma unroll
        for (int nt = 0; nt < 4; ++nt) {
            const __nv_bfloat16 *p = Bs + (wn * 32 + nt * 8 + gid) * LDA + k0 + 2 * tig;
            b[nt][0] = *(const u32 *)p;
            b[nt][1] = *(const u32 *)(p + 8);
        }
#pragma unroll
        for (int mt = 0; mt < 4; ++mt)
#pragma unroll
            for (int nt = 0; nt < 4; ++nt) mma16816(acc[mt][nt], a[mt], b[nt]);
    }
    float bb0[4], bb1[4];
#pragma unroll
    for (int nt = 0; nt < 4; ++nt) {
        int n = g0 + wn * 32 + nt * 8 + 2 * tig;
        bb0[nt] = bih1[n] + bhh1[n];
        bb1[nt] = bih1[n + 1] + bhh1[n + 1];
    }
#pragma unroll
    for (int mt = 0; mt < 4; ++mt) {
        size_t row0 = bt0 + wm * 64 + mt * 16 + gid;
#pragma unroll
        for (int nt = 0; nt < 4; ++nt) {
            int n = g0 + wn * 32 + nt * 8 + 2 * tig;
            *reinterpret_cast<__nv_bfloat162 *>(g_xg1 + row0 * GG + n) =
                __floats2bfloat162_rn(acc[mt][nt][0] + bb0[nt], acc[mt][nt][1] + bb1[nt]);
            *reinterpret_cast<__nv_bfloat162 *>(g_xg1 + (row0 + 8) * GG + n) =
                __floats2bfloat162_rn(acc[mt][nt][2] + bb0[nt], acc[mt][nt][3] + bb1[nt]);
        }
    }
}

// ================= K2: layer-1 LSTM, transposed HMMA recurrence, xg double-buffered ==============
extern "C" __global__ void __launch_bounds__(256, 1)
k_lstm1(const float *__restrict__ Whh1) {
    __shared__ __nv_bfloat16 hbuf[2 * ROWS * PADH];
    __shared__ __nv_bfloat16 xbuf[2 * ROWS * XPAD];
    const int tid = threadIdx.x;
    const int w = tid >> 5, lane = tid & 31, gid = lane >> 2, tig = lane & 3;
    const int rb = blockIdx.x * ROWS;
    const int u0 = w * 16 + gid, u1 = u0 + 8;
    const int r0 = 2 * tig, r1 = r0 + 1;

    u32 a[4][8][4];
#pragma unroll
    for (int g = 0; g < 4; ++g) {
        const int gr0 = g * 128 + u0, gr1 = g * 128 + u1;
#pragma unroll
        for (int kt = 0; kt < 8; ++kt) {
            const int k = kt * 16 + 2 * tig;
            a[g][kt][0] = pbf2(Whh1[(size_t)gr0 * HH + k], Whh1[(size_t)gr0 * HH + k + 1]);
            a[g][kt][1] = pbf2(Whh1[(size_t)gr1 * HH + k], Whh1[(size_t)gr1 * HH + k + 1]);
            a[g][kt][2] = pbf2(Whh1[(size_t)gr0 * HH + k + 8], Whh1[(size_t)gr0 * HH + k + 9]);
            a[g][kt][3] = pbf2(Whh1[(size_t)gr1 * HH + k + 8], Whh1[(size_t)gr1 * HH + k + 9]);
        }
    }
    for (int i = tid; i < 2 * ROWS * PADH / 2; i += 256) ((u32 *)hbuf)[i] = 0u;
    // preload xg(t=0)
    for (int i = tid; i < 512; i += 256) {
        int row = i >> 6, col = i & 63;
        uint4 v = *(const uint4 *)(g_xg1 + ((size_t)(rb + row) * TT) * GG + col * 8);
        *(uint4 *)&xbuf[row * XPAD + col * 8] = v;
    }
    float c[4] = {0.f, 0.f, 0.f, 0.f};
    __syncthreads();

#pragma unroll 1
    for (int t = 0; t < TT; ++t) {
        const int tn = t + 1;
        // prefetch next step's xg (consumed after this step's barrier)
        uint4 pf0, pf1;
        if (tn < TT) {
            int i0 = tid, i1 = tid + 256;
            pf0 = *(const uint4 *)(g_xg1 + ((size_t)(rb + (i0 >> 6)) * TT + tn) * GG + (i0 & 63) * 8);
            pf1 = *(const uint4 *)(g_xg1 + ((size_t)(rb + (i1 >> 6)) * TT + tn) * GG + (i1 & 63) * 8);
        }
        const __nv_bfloat16 *hb = hbuf + (t & 1) * ROWS * PADH;
        __nv_bfloat16 *hn = hbuf + ((t + 1) & 1) * ROWS * PADH;
        u32 b[8][2];
#pragma unroll
        for (int kt = 0; kt < 8; ++kt) {
            const int base = gid * PADH + kt * 16 + 2 * tig;
            b[kt][0] = *(const u32 *)&hb[base];
            b[kt][1] = *(const u32 *)&hb[base + 8];
        }
        float acc[4][4];
#pragma unroll
        for (int g = 0; g < 4; ++g) { acc[g][0] = acc[g][1] = acc[g][2] = acc[g][3] = 0.f; }
#pragma unroll
        for (int kt = 0; kt < 8; ++kt)
#pragma unroll
            for (int g = 0; g < 4; ++g) mma16816(acc[g], a[g][kt], b[kt]);
        // add precomputed input gates
        const __nv_bfloat16 *xb = xbuf + (t & 1) * ROWS * XPAD;
#pragma unroll
        for (int g = 0; g < 4; ++g) {
            acc[g][0] += __bfloat162float(xb[r0 * XPAD + g * 128 + u0]);
            acc[g][1] += __bfloat162float(xb[r1 * XPAD + g * 128 + u0]);
            acc[g][2] += __bfloat162float(xb[r0 * XPAD + g * 128 + u1]);
            acc[g][3] += __bfloat162float(xb[r1 * XPAD + g * 128 + u1]);
        }
        float h[4];
#pragma unroll
        for (int s = 0; s < 4; ++s) {
            c[s] = sigm(acc[1][s]) * c[s] + sigm(acc[0][s]) * tanha(acc[2][s]);
            h[s] = sigm(acc[3][s]) * tanha(c[s]);
        }
        hn[r0 * PADH + u0] = __float2bfloat16(h[0]);
        hn[r1 * PADH + u0] = __float2bfloat16(h[1]);
        hn[r0 * PADH + u1] = __float2bfloat16(h[2]);
        hn[r1 * PADH + u1] = __float2bfloat16(h[3]);
        if (tn < TT) {
            __nv_bfloat16 *xn = xbuf + (tn & 1) * ROWS * XPAD;
            int i0 = tid, i1 = tid + 256;
            *(uint4 *)&xn[(i0 >> 6) * XPAD + (i0 & 63) * 8] = pf0;
            *(uint4 *)&xn[(i1 >> 6) * XPAD + (i1 & 63) * 8] = pf1;
        } else {
            g_h1f[(rb + r0) * HH + u0] = h[0];
            g_h1f[(rb + r1) * HH + u0] = h[1];
            g_h1f[(rb + r0) * HH + u1] = h[2];
            g_h1f[(rb + r1) * HH + u1] = h[3];
        }
        __syncthreads();
    }
}

// ================= K3: classifier MLP + double softmax =================
extern "C" __global__ void __launch_bounds__(128)
k_cls(const float *__restrict__ W1, const float *__restrict__ b1,
      const float *__restrict__ W2, const float *__restrict__ b2,
      const float *__restrict__ W3, const float *__restrict__ b3,
      float *__restrict__ out) {
    __shared__ float hb[128], z1[128], z2[64], z3[8];
    const int tid = threadIdx.x;
    const int row = blockIdx.x;
    hb[tid] = g_h1f[row * HH + tid];
    __syncthreads();
    float a = b1[tid];
#pragma unroll 4
    for (int k = 0; k < 128; ++k) a = fmaf(W1[tid * 128 + k], hb[k], a);
    z1[tid] = fmaxf(a, 0.f);
    __syncthreads();
    if (tid < 64) {
        float s = b2[tid];
#pragma unroll 4
        for (int k = 0; k < 128; ++k) s = fmaf(W2[tid * 128 + k], z1[k], s);
        z2[tid] = fmaxf(s, 0.f);
    }
    __syncthreads();
    if (tid < 6) {
        float s = b3[tid];
#pragma unroll 4
        for (int k = 0; k < 64; ++k) s = fmaf(W3[tid * 64 + k], z2[k], s);
        z3[tid] = s;
    }
    __syncthreads();
    if (tid == 0) {
        float v[6];
#pragma unroll
        for (int i = 0; i < 6; ++i) v[i] = z3[i];
#pragma unroll
        for (int p = 0; p < 2; ++p) {
            float m = v[0];
            for (int i = 1; i < 6; ++i) m = fmaxf(m, v[i]);
            float s = 0.f;
            for (int i = 0; i < 6; ++i) { v[i] = expf(v[i] - m); s += v[i]; }
            float inv = 1.f / s;
            for (int i = 0; i < 6; ++i) v[i] *= inv;
        }
        for (int i = 0; i < 6; ++i) out[row * 6 + i] = v[i];
    }
}

extern "C" void kernel_launch(void *const *d_in, const int *in_sizes, int n_in,
                              void *d_out, int out_size) {
    const float *x = (const float *)d_in[0];
    const float *Wih0 = (const float *)d_in[1];
    const float *Whh0 = (const float *)d_in[2];
    const float *bih0 = (const float *)d_in[3];
    const float *bhh0 = (const float *)d_in[4];
    const float *Wih1 = (const float *)d_in[5];
    const float *Whh1 = (const float *)d_in[6];
    const float *bih1 = (const float *)d_in[7];
    const float *bhh1 = (const float *)d_in[8];
    const float *W1 = (const float *)d_in[9];
    const float *b1 = (const float *)d_in[10];
    const float *W2 = (const float *)d_in[11];
    const float *b2 = (const float *)d_in[12];
    const float *W3 = (const float *)d_in[13];
    const float *b3 = (const float *)d_in[14];
    float *out = (float *)d_out;

    const int SMEM0 = 8 * FPAD * 4 + 2 * ROWS * PADH * 2;  // 70016
    const int SMEM1 = 2 * 128 * LDA * 2;                   // 69632
    cudaFuncSetAttribute(k_lstm0, cudaFuncAttributeMaxDynamicSharedMemorySize, SMEM0);
    cudaFuncSetAttribute(k_gemm1, cudaFuncAttributeMaxDynamicSharedMemorySize, SMEM1);

    k_lstm0<<<NBLK, 256, SMEM0>>>(x, Wih0, Whh0, bih0, bhh0);
    k_gemm1<<<dim3((BB * TT) / 128, GG / 128), 256, SMEM1>>>(Wih1, bih1, bhh1);
    k_lstm1<<<NBLK, 256>>>(Whh1);
    k_cls<<<BB, 128>>>(W1, b1, W2, b2, W3, b3, out);
}